// round 1
// baseline (speedup 1.0000x reference)
#include <cuda_runtime.h>
#include <math.h>

// Problem constants
#define BATCH 2
#define SEQ   2048
#define HID   2048
#define NHEAD 16
#define HDIM  128
#define FFD   8192
#define ROWS  (BATCH*SEQ)       // 4096
#define RMS_EPS 1e-5f

// ---------------------------------------------------------------------------
// Scratch (static __device__ arrays — allocation-free per harness rules)
// ---------------------------------------------------------------------------
__device__ float g_qn [ROWS*HID];
__device__ float g_q  [ROWS*HID];
__device__ float g_k  [ROWS*HID];
__device__ float g_v  [ROWS*HID];
__device__ float g_att[ROWS*HID];
__device__ float g_mod[ROWS*HID];
__device__ float g_t1 [ROWS*HID];
__device__ float g_t2 [ROWS*HID];
__device__ float g_x  [ROWS*HID];
__device__ float g_h  [ROWS*HID];
__device__ float g_gate[(size_t)ROWS*FFD];
__device__ float g_up  [(size_t)ROWS*FFD];
__device__ float g_sc  [(size_t)BATCH*NHEAD*SEQ*SEQ];   // 512 MB attention scores

// ---------------------------------------------------------------------------
// Reductions (blockDim.x == 256 assumed)
// ---------------------------------------------------------------------------
__device__ __forceinline__ float warpReduceSum(float v) {
#pragma unroll
    for (int o = 16; o; o >>= 1) v += __shfl_xor_sync(0xffffffffu, v, o);
    return v;
}
__device__ __forceinline__ float warpReduceMax(float v) {
#pragma unroll
    for (int o = 16; o; o >>= 1) v = fmaxf(v, __shfl_xor_sync(0xffffffffu, v, o));
    return v;
}
__device__ __forceinline__ float blockReduceSum256(float v) {
    __shared__ float sh[8];
    v = warpReduceSum(v);
    __syncthreads();
    if ((threadIdx.x & 31) == 0) sh[threadIdx.x >> 5] = v;
    __syncthreads();
    float r = 0.f;
#pragma unroll
    for (int i = 0; i < 8; i++) r += sh[i];
    return r;
}
__device__ __forceinline__ float blockReduceMax256(float v) {
    __shared__ float sh[8];
    v = warpReduceMax(v);
    __syncthreads();
    if ((threadIdx.x & 31) == 0) sh[threadIdx.x >> 5] = v;
    __syncthreads();
    float r = sh[0];
#pragma unroll
    for (int i = 1; i < 8; i++) r = fmaxf(r, sh[i]);
    return r;
}

// ---------------------------------------------------------------------------
// SGEMM: C = alpha * A * op(B)
//   A: [M,K] row-major, lda = row stride
//   BT=true : B is [N,K] row-major (C = A * B^T)      -- weight GEMMs, QK^T
//   BT=false: B is [K,N] row-major (C = A * B)        -- P*V
// 128x128x16 tiles, 8x8 per thread, smem double buffer, 1 sync per k-tile.
// blockIdx.z = batch, with linear strides sA/sB/sC.
// All dims are multiples of the tile sizes for this problem — no bounds checks.
// ---------------------------------------------------------------------------
template<bool BT>
__global__ __launch_bounds__(256, 2)
void sgemm_kernel(const float* __restrict__ Ag, const float* __restrict__ Bg,
                  float* __restrict__ Cg,
                  int M, int N, int K, int lda, int ldb, int ldc, float alpha,
                  long long sA, long long sB, long long sC)
{
    const float* A = Ag + blockIdx.z * sA;
    const float* B = Bg + blockIdx.z * sB;
    float*       C = Cg + blockIdx.z * sC;

    const int bm = blockIdx.y << 7;
    const int bn = blockIdx.x << 7;
    const int tid = threadIdx.x;

    __shared__ float As[2][16][132];
    __shared__ float Bs[2][16][132];

    const int ar = tid >> 2;          // 0..63 : row within A tile (and B tile if BT)
    const int ac = (tid & 3) << 2;    // 0,4,8,12 : k offset
    const int br = tid >> 5;          // 0..7  : k row within B tile (NN)
    const int bc = (tid & 31) << 2;   // 0..124: n offset (NN)

    const int wy = (tid >> 4) << 2;   // 0..60 thread row offset
    const int wx = (tid & 15) << 2;   // 0..60 thread col offset

    const float* Aptr = A + (long long)(bm + ar) * lda + ac;
    const float* Bptr = BT ? (B + (long long)(bn + ar) * ldb + ac)
                           : (B + (long long)br * ldb + bn + bc);

    float acc[8][8];
#pragma unroll
    for (int i = 0; i < 8; i++)
#pragma unroll
        for (int j = 0; j < 8; j++) acc[i][j] = 0.f;

    // prologue: load k-tile 0
    float4 pa0 = *(const float4*)(Aptr);
    float4 pa1 = *(const float4*)(Aptr + (long long)64 * lda);
    float4 pb0, pb1;
    if (BT) {
        pb0 = *(const float4*)(Bptr);
        pb1 = *(const float4*)(Bptr + (long long)64 * ldb);
    } else {
        pb0 = *(const float4*)(Bptr);
        pb1 = *(const float4*)(Bptr + (long long)8 * ldb);
    }
    As[0][ac+0][ar]    = pa0.x; As[0][ac+1][ar]    = pa0.y; As[0][ac+2][ar]    = pa0.z; As[0][ac+3][ar]    = pa0.w;
    As[0][ac+0][ar+64] = pa1.x; As[0][ac+1][ar+64] = pa1.y; As[0][ac+2][ar+64] = pa1.z; As[0][ac+3][ar+64] = pa1.w;
    if (BT) {
        Bs[0][ac+0][ar]    = pb0.x; Bs[0][ac+1][ar]    = pb0.y; Bs[0][ac+2][ar]    = pb0.z; Bs[0][ac+3][ar]    = pb0.w;
        Bs[0][ac+0][ar+64] = pb1.x; Bs[0][ac+1][ar+64] = pb1.y; Bs[0][ac+2][ar+64] = pb1.z; Bs[0][ac+3][ar+64] = pb1.w;
    } else {
        *(float4*)&Bs[0][br][bc]     = pb0;
        *(float4*)&Bs[0][br + 8][bc] = pb1;
    }
    __syncthreads();

    const int nk = K >> 4;
    for (int kt = 0; kt < nk; kt++) {
        const int buf = kt & 1;
        if (kt + 1 < nk) {  // prefetch next tile into registers
            const float* Ap = Aptr + (kt + 1) * 16;
            pa0 = *(const float4*)(Ap);
            pa1 = *(const float4*)(Ap + (long long)64 * lda);
            if (BT) {
                const float* Bp = Bptr + (kt + 1) * 16;
                pb0 = *(const float4*)(Bp);
                pb1 = *(const float4*)(Bp + (long long)64 * ldb);
            } else {
                const float* Bp = Bptr + (long long)(kt + 1) * 16 * ldb;
                pb0 = *(const float4*)(Bp);
                pb1 = *(const float4*)(Bp + (long long)8 * ldb);
            }
        }
#pragma unroll
        for (int k = 0; k < 16; k++) {
            float4 a0 = *(const float4*)&As[buf][k][wy];
            float4 a1 = *(const float4*)&As[buf][k][wy + 64];
            float4 b0 = *(const float4*)&Bs[buf][k][wx];
            float4 b1 = *(const float4*)&Bs[buf][k][wx + 64];
            float av[8] = {a0.x,a0.y,a0.z,a0.w,a1.x,a1.y,a1.z,a1.w};
            float bv[8] = {b0.x,b0.y,b0.z,b0.w,b1.x,b1.y,b1.z,b1.w};
#pragma unroll
            for (int i = 0; i < 8; i++)
#pragma unroll
                for (int j = 0; j < 8; j++)
                    acc[i][j] = fmaf(av[i], bv[j], acc[i][j]);
        }
        if (kt + 1 < nk) {  // store prefetched tile into other buffer
            const int nb = buf ^ 1;
            As[nb][ac+0][ar]    = pa0.x; As[nb][ac+1][ar]    = pa0.y; As[nb][ac+2][ar]    = pa0.z; As[nb][ac+3][ar]    = pa0.w;
            As[nb][ac+0][ar+64] = pa1.x; As[nb][ac+1][ar+64] = pa1.y; As[nb][ac+2][ar+64] = pa1.z; As[nb][ac+3][ar+64] = pa1.w;
            if (BT) {
                Bs[nb][ac+0][ar]    = pb0.x; Bs[nb][ac+1][ar]    = pb0.y; Bs[nb][ac+2][ar]    = pb0.z; Bs[nb][ac+3][ar]    = pb0.w;
                Bs[nb][ac+0][ar+64] = pb1.x; Bs[nb][ac+1][ar+64] = pb1.y; Bs[nb][ac+2][ar+64] = pb1.z; Bs[nb][ac+3][ar+64] = pb1.w;
            } else {
                *(float4*)&Bs[nb][br][bc]     = pb0;
                *(float4*)&Bs[nb][br + 8][bc] = pb1;
            }
            __syncthreads();
        }
    }

    // epilogue
#pragma unroll
    for (int i = 0; i < 8; i++) {
        const int row = bm + wy + (i & 3) + ((i >> 2) << 6);
        float* cp = C + (long long)row * ldc + bn + wx;
        float4 o0 = make_float4(acc[i][0]*alpha, acc[i][1]*alpha, acc[i][2]*alpha, acc[i][3]*alpha);
        float4 o1 = make_float4(acc[i][4]*alpha, acc[i][5]*alpha, acc[i][6]*alpha, acc[i][7]*alpha);
        *(float4*)(cp)      = o0;
        *(float4*)(cp + 64) = o1;
    }
}

// ---------------------------------------------------------------------------
// RMSNorm: out = x * rsqrt(mean(x^2) + eps) * w     (one block per row)
// ---------------------------------------------------------------------------
__global__ __launch_bounds__(256)
void rmsnorm_kernel(const float* __restrict__ in, const float* __restrict__ w,
                    float* __restrict__ out)
{
    const long long base = (long long)blockIdx.x * HID;
    const float4* xin = (const float4*)(in + base);
    float ss = 0.f;
#pragma unroll
    for (int i = threadIdx.x; i < HID/4; i += 256) {
        float4 v = xin[i];
        ss += v.x*v.x + v.y*v.y + v.z*v.z + v.w*v.w;
    }
    ss = blockReduceSum256(ss);
    const float r = rsqrtf(ss * (1.f/HID) + RMS_EPS);
#pragma unroll
    for (int i = threadIdx.x; i < HID/4; i += 256) {
        float4 v = xin[i];
        float4 ww = ((const float4*)w)[i];
        ((float4*)(out + base))[i] =
            make_float4(v.x*r*ww.x, v.y*r*ww.y, v.z*r*ww.z, v.w*r*ww.w);
    }
}

// x = x + rms(x, w)  (in place): x *= (1 + r*w)
__global__ __launch_bounds__(256)
void rmsadd_kernel(float* __restrict__ x, const float* __restrict__ w)
{
    const long long base = (long long)blockIdx.x * HID;
    float4* xp = (float4*)(x + base);
    float ss = 0.f;
#pragma unroll
    for (int i = threadIdx.x; i < HID/4; i += 256) {
        float4 v = xp[i];
        ss += v.x*v.x + v.y*v.y + v.z*v.z + v.w*v.w;
    }
    ss = blockReduceSum256(ss);
    const float r = rsqrtf(ss * (1.f/HID) + RMS_EPS);
#pragma unroll
    for (int i = threadIdx.x; i < HID/4; i += 256) {
        float4 v = xp[i];
        float4 ww = ((const float4*)w)[i];
        xp[i] = make_float4(v.x*(1.f + r*ww.x), v.y*(1.f + r*ww.y),
                            v.z*(1.f + r*ww.z), v.w*(1.f + r*ww.w));
    }
}

// ---------------------------------------------------------------------------
// RoPE (rotate-half) in place on [ROWS, HID] viewed as [row][head*128+d]
// ---------------------------------------------------------------------------
__global__ void rope_kernel(float* __restrict__ t)
{
    const int idx = blockIdx.x * blockDim.x + threadIdx.x;
    if (idx >= ROWS * NHEAD * (HDIM/2)) return;
    const int j   = idx & 63;
    const int h   = (idx >> 6) & (NHEAD - 1);
    const int row = idx >> 10;
    const int pos = row & (SEQ - 1);
    const float inv = (float)exp(-(double)(2*j) / (double)HDIM * log(10000.0));
    const float f = (float)pos * inv;
    float s_, c;
    sincosf(f, &s_, &c);
    float* p = t + (long long)row * HID + h * HDIM + j;
    const float q0 = p[0], q1 = p[HDIM/2];
    p[0]      = q0 * c - q1 * s_;
    p[HDIM/2] = q1 * c + q0 * s_;
}

// ---------------------------------------------------------------------------
// Softmax over rows of scores (scale pre-applied in GEMM alpha); adds mask.
// grid = (SEQ, BATCH*NHEAD), 256 threads, 8 elems/thread kept in registers.
// ---------------------------------------------------------------------------
__global__ __launch_bounds__(256)
void softmax_kernel(float* __restrict__ sc, const float* __restrict__ mask)
{
    float* p = sc + ((long long)blockIdx.y * SEQ + blockIdx.x) * SEQ;
    const float* mp = mask + (long long)blockIdx.x * SEQ;
    const int t = threadIdx.x * 8;
    float4 a = *(const float4*)(p + t);
    float4 b = *(const float4*)(p + t + 4);
    float4 ma = *(const float4*)(mp + t);
    float4 mb = *(const float4*)(mp + t + 4);
    a.x += ma.x; a.y += ma.y; a.z += ma.z; a.w += ma.w;
    b.x += mb.x; b.y += mb.y; b.z += mb.z; b.w += mb.w;
    float mx = fmaxf(fmaxf(fmaxf(a.x,a.y),fmaxf(a.z,a.w)),
                     fmaxf(fmaxf(b.x,b.y),fmaxf(b.z,b.w)));
    mx = blockReduceMax256(mx);
    a.x = expf(a.x - mx); a.y = expf(a.y - mx); a.z = expf(a.z - mx); a.w = expf(a.w - mx);
    b.x = expf(b.x - mx); b.y = expf(b.y - mx); b.z = expf(b.z - mx); b.w = expf(b.w - mx);
    float s = a.x + a.y + a.z + a.w + b.x + b.y + b.z + b.w;
    s = blockReduceSum256(s);
    const float invs = 1.f / s;
    a.x *= invs; a.y *= invs; a.z *= invs; a.w *= invs;
    b.x *= invs; b.y *= invs; b.z *= invs; b.w *= invs;
    *(float4*)(p + t)     = a;
    *(float4*)(p + t + 4) = b;
}

// ---------------------------------------------------------------------------
// Elementwise kernels (float4, one pass)
// ---------------------------------------------------------------------------
__device__ __forceinline__ float sigm(float z) { return 1.f / (1.f + expf(-z)); }

// out = sigmoid(g + bias) * h        (delta / highway)
__global__ void highway_kernel(const float* __restrict__ g, const float* __restrict__ hh,
                               const float* __restrict__ bias, float* __restrict__ out, int n4)
{
    const int i = blockIdx.x * blockDim.x + threadIdx.x;
    if (i >= n4) return;
    float4 gv = ((const float4*)g)[i];
    float4 hv = ((const float4*)hh)[i];
    float4 bv = ((const float4*)bias)[i & (HID/4 - 1)];
    ((float4*)out)[i] = make_float4(hv.x * sigm(gv.x + bv.x), hv.y * sigm(gv.y + bv.y),
                                    hv.z * sigm(gv.z + bv.z), hv.w * sigm(gv.w + bv.w));
}

// out = xm + mod + sigmoid(g + bias) * h
__global__ void combinex_kernel(const float* __restrict__ xm, const float* __restrict__ mod,
                                const float* __restrict__ g, const float* __restrict__ hh,
                                const float* __restrict__ bias, float* __restrict__ out, int n4)
{
    const int i = blockIdx.x * blockDim.x + threadIdx.x;
    if (i >= n4) return;
    float4 xv = ((const float4*)xm)[i];
    float4 mv = ((const float4*)mod)[i];
    float4 gv = ((const float4*)g)[i];
    float4 hv = ((const float4*)hh)[i];
    float4 bv = ((const float4*)bias)[i & (HID/4 - 1)];
    ((float4*)out)[i] = make_float4(xv.x + mv.x + hv.x * sigm(gv.x + bv.x),
                                    xv.y + mv.y + hv.y * sigm(gv.y + bv.y),
                                    xv.z + mv.z + hv.z * sigm(gv.z + bv.z),
                                    xv.w + mv.w + hv.w * sigm(gv.w + bv.w));
}

// g = silu(g) * u   (in place on g)
__global__ void silumul_kernel(float* __restrict__ g, const float* __restrict__ u, int n4)
{
    const int i = blockIdx.x * blockDim.x + threadIdx.x;
    if (i >= n4) return;
    float4 gv = ((float4*)g)[i];
    float4 uv = ((const float4*)u)[i];
    ((float4*)g)[i] = make_float4(gv.x * sigm(gv.x) * uv.x, gv.y * sigm(gv.y) * uv.y,
                                  gv.z * sigm(gv.z) * uv.z, gv.w * sigm(gv.w) * uv.w);
}

// out = a + b
__global__ void add2_kernel(const float* __restrict__ a, const float* __restrict__ b,
                            float* __restrict__ out, int n4)
{
    const int i = blockIdx.x * blockDim.x + threadIdx.x;
    if (i >= n4) return;
    float4 av = ((const float4*)a)[i];
    float4 bv = ((const float4*)b)[i];
    ((float4*)out)[i] = make_float4(av.x + bv.x, av.y + bv.y, av.z + bv.z, av.w + bv.w);
}

// ---------------------------------------------------------------------------
// Launch
// ---------------------------------------------------------------------------
extern "C" void kernel_launch(void* const* d_in, const int* in_sizes, int n_in,
                              void* d_out, int out_size)
{
    const float* x_mod      = (const float*)d_in[0];
    const float* x_back     = (const float*)d_in[1];
    const float* mask       = (const float*)d_in[2];
    const float* wq         = (const float*)d_in[3];
    const float* wk         = (const float*)d_in[4];
    const float* wv         = (const float*)d_in[5];
    const float* wo         = (const float*)d_in[6];
    const float* cross_ln_w = (const float*)d_in[7];
    const float* fb_w       = (const float*)d_in[8];
    const float* fb_g       = (const float*)d_in[9];
    const float* fb_gb      = (const float*)d_in[10];
    const float* dr_w       = (const float*)d_in[11];
    const float* dr_g       = (const float*)d_in[12];
    const float* dr_gb      = (const float*)d_in[13];
    const float* in_ln_w    = (const float*)d_in[14];
    const float* post_ln_w  = (const float*)d_in[15];
    const float* w_gate     = (const float*)d_in[16];
    const float* w_up       = (const float*)d_in[17];
    const float* w_down     = (const float*)d_in[18];

    float* outx = (float*)d_out;                       // x  first in the tuple
    float* outd = outx + (size_t)ROWS * HID;           // delta second

    float *qn,*q,*k,*v,*att,*mod,*t1,*t2,*x,*h,*gg,*uu,*sc;
    cudaGetSymbolAddress((void**)&qn,  g_qn);
    cudaGetSymbolAddress((void**)&q,   g_q);
    cudaGetSymbolAddress((void**)&k,   g_k);
    cudaGetSymbolAddress((void**)&v,   g_v);
    cudaGetSymbolAddress((void**)&att, g_att);
    cudaGetSymbolAddress((void**)&mod, g_mod);
    cudaGetSymbolAddress((void**)&t1,  g_t1);
    cudaGetSymbolAddress((void**)&t2,  g_t2);
    cudaGetSymbolAddress((void**)&x,   g_x);
    cudaGetSymbolAddress((void**)&h,   g_h);
    cudaGetSymbolAddress((void**)&gg,  g_gate);
    cudaGetSymbolAddress((void**)&uu,  g_up);
    cudaGetSymbolAddress((void**)&sc,  g_sc);

    const float ATT_SCALE = 0.08838834764831845f;   // 128^-0.5
    const int n4h = ROWS * HID / 4;                  // 2,097,152
    const int n4f = (int)((size_t)ROWS * FFD / 4);   // 8,388,608
    const dim3 B256(256);
    const dim3 gHH(HID/128, ROWS/128);               // 4096x2048 GEMM grid
    const dim3 gFF(FFD/128, ROWS/128);

    // ---- cross-attention inputs ----
    rmsnorm_kernel<<<ROWS, B256>>>(x_mod, cross_ln_w, qn);
    sgemm_kernel<true><<<gHH, B256>>>(qn,     wq, q, ROWS, HID, HID, HID, HID, HID, 1.f, 0, 0, 0);
    sgemm_kernel<true><<<gHH, B256>>>(x_back, wk, k, ROWS, HID, HID, HID, HID, HID, 1.f, 0, 0, 0);
    sgemm_kernel<true><<<gHH, B256>>>(x_back, wv, v, ROWS, HID, HID, HID, HID, HID, 1.f, 0, 0, 0);

    const int ropeN = ROWS * NHEAD * (HDIM/2);
    rope_kernel<<<(ropeN + 255)/256, B256>>>(q);
    rope_kernel<<<(ropeN + 255)/256, B256>>>(k);

    // ---- attention: scores = scale * Q K^T ; softmax(+mask) ; out = P V ----
    for (int b = 0; b < BATCH; b++) {
        dim3 gq(SEQ/128, SEQ/128, NHEAD);
        sgemm_kernel<true><<<gq, B256>>>(
            q + (size_t)b*SEQ*HID, k + (size_t)b*SEQ*HID, sc + (size_t)b*NHEAD*SEQ*SEQ,
            SEQ, SEQ, HDIM, HID, HID, SEQ, ATT_SCALE,
            128, 128, (long long)SEQ*SEQ);
    }
    softmax_kernel<<<dim3(SEQ, BATCH*NHEAD), B256>>>(sc, mask);
    for (int b = 0; b < BATCH; b++) {
        dim3 gp(HDIM/128, SEQ/128, NHEAD);
        sgemm_kernel<false><<<gp, B256>>>(
            sc + (size_t)b*NHEAD*SEQ*SEQ, v + (size_t)b*SEQ*HID, att + (size_t)b*SEQ*HID,
            SEQ, HDIM, SEQ, SEQ, HID, HID, 1.f,
            (long long)SEQ*SEQ, 128, 128);
    }
    sgemm_kernel<true><<<gHH, B256>>>(att, wo, mod, ROWS, HID, HID, HID, HID, HID, 1.f, 0, 0, 0);

    // ---- feedback highway -> delta (second output) ----
    sgemm_kernel<true><<<gHH, B256>>>(x_mod, fb_g, t1, ROWS, HID, HID, HID, HID, HID, 1.f, 0, 0, 0);
    sgemm_kernel<true><<<gHH, B256>>>(x_mod, fb_w, t2, ROWS, HID, HID, HID, HID, HID, 1.f, 0, 0, 0);
    highway_kernel<<<n4h/256, B256>>>(t1, t2, fb_gb, outd, n4h);

    // ---- driver highway, fused into x = x_mod + mod + drv ----
    sgemm_kernel<true><<<gHH, B256>>>(x_back, dr_g, t1, ROWS, HID, HID, HID, HID, HID, 1.f, 0, 0, 0);
    sgemm_kernel<true><<<gHH, B256>>>(x_back, dr_w, t2, ROWS, HID, HID, HID, HID, HID, 1.f, 0, 0, 0);
    combinex_kernel<<<n4h/256, B256>>>(x_mod, mod, t1, t2, dr_gb, x, n4h);

    // ---- decoder: x += rms(x); mlp on rms(x) ----
    rmsadd_kernel<<<ROWS, B256>>>(x, in_ln_w);
    rmsnorm_kernel<<<ROWS, B256>>>(x, post_ln_w, h);

    sgemm_kernel<true><<<gFF, B256>>>(h, w_gate, gg, ROWS, FFD, HID, HID, HID, FFD, 1.f, 0, 0, 0);
    sgemm_kernel<true><<<gFF, B256>>>(h, w_up,   uu, ROWS, FFD, HID, HID, HID, FFD, 1.f, 0, 0, 0);
    silumul_kernel<<<n4f/256, B256>>>(gg, uu, n4f);
    sgemm_kernel<true><<<gHH, B256>>>(gg, w_down, mod, ROWS, HID, FFD, FFD, FFD, HID, 1.f, 0, 0, 0);

    add2_kernel<<<n4h/256, B256>>>(x, mod, outx, n4h);
}